// round 15
// baseline (speedup 1.0000x reference)
#include <cuda_runtime.h>
#include <cuda_fp16.h>
#include <math.h>
#include <stdint.h>

#define NB 2
#define NC 256
#define NS 32768
#define CTX 77
#define HEADS 8
#define JP 80
#define NP 640
#define M_TOTAL 65536
#define EPS 1e-5f
#define ATT_SCALE 0.17677669529663687f

// ---------------- scratch ----------------
__device__ float g_part[16 * 1024 * 2];
__device__ float g_stat[16][2];
__device__ float g_cn[NB * CTX * 768];
__device__ float g_v[NB * HEADS * CTX * 32];
__device__ __half g_wqt[NB * 256 * 256];
__device__ float g_qbias[NB * 256];
__device__ __half g_k2[NB * NP * 40];             // pads stay zero from static init
__device__ __half g_v2[NB * 256 * 88];            // V^T per head: [b][h*32+d][j]
__device__ __half g_wot[256 * 256];               // Wo^T fp16: [c][u]
__device__ __half g_xt[(size_t)M_TOTAL * NC];
__device__ __half g_p[(size_t)M_TOTAL * NP];

// ---------------- helpers ----------------
__device__ __forceinline__ uint32_t smem_u32(const void* p) {
    uint32_t a;
    asm("{ .reg .u64 t; cvta.to.shared.u64 t, %1; cvt.u32.u64 %0, t; }" : "=r"(a) : "l"(p));
    return a;
}
__device__ __forceinline__ void cp16(uint32_t dst, const void* src) {
    asm volatile("cp.async.ca.shared.global [%0], [%1], 16;" :: "r"(dst), "l"(src));
}
__device__ __forceinline__ void cp_commit() { asm volatile("cp.async.commit_group;" ::: "memory"); }
__device__ __forceinline__ void cp_wait0() { asm volatile("cp.async.wait_group 0;" ::: "memory"); }
__device__ __forceinline__ void cp_wait1() { asm volatile("cp.async.wait_group 1;" ::: "memory"); }

__device__ __forceinline__ void mma16(float* c, const uint32_t* a, uint32_t b0, uint32_t b1) {
    asm volatile("mma.sync.aligned.m16n8k16.row.col.f32.f16.f16.f32 "
                 "{%0,%1,%2,%3},{%4,%5,%6,%7},{%8,%9},{%0,%1,%2,%3};"
                 : "+f"(c[0]), "+f"(c[1]), "+f"(c[2]), "+f"(c[3])
                 : "r"(a[0]), "r"(a[1]), "r"(a[2]), "r"(a[3]), "r"(b0), "r"(b1));
}
__device__ __forceinline__ void ldsm4(uint32_t* r, uint32_t addr) {
    asm volatile("ldmatrix.sync.aligned.m8n8.x4.shared.b16 {%0,%1,%2,%3}, [%4];"
                 : "=r"(r[0]), "=r"(r[1]), "=r"(r[2]), "=r"(r[3]) : "r"(addr));
}

// gemm1_fused smem layout (bytes)
#define OFF_A  0u
#define OFF_QT 67584u
#define OFF_KS 135168u
#define OFF_B0 186368u
#define OFF_B1 196608u
#define SMEM1  206848

// gemm2_fused smem layout (bytes)
#define F2_U   0u          // U: 128 x 264 halves = 67584
#define F2_VT  67584u      // Vt: 256 x 88 halves = 45056
#define F2_P0  112640u     // P pair buf: 128 x 184 halves = 47104
#define F2_P1  159744u
#define F2_W0  112640u     // phase-2 Wo tiles (reuse P area): 256 x 40 x 2 = 20480
#define F2_W1  133120u
#define SMEM2F 206848

// ---------------- xt_k ----------------
__global__ void xt_k(const float* __restrict__ x) {
    __shared__ float tl[32][33];
    __shared__ float red[8][2];
    int tx = threadIdx.x, ty = threadIdx.y;
    int s0 = blockIdx.x * 32, g = blockIdx.y, b = blockIdx.z;
    int c0 = g * 32;
    float s = 0.f, sq = 0.f;
#pragma unroll
    for (int i = ty; i < 32; i += 8) {
        float v = x[((size_t)b * 256 + c0 + i) * 32768 + s0 + tx];
        tl[i][tx] = v;
        s += v; sq += v * v;
    }
    __syncthreads();
#pragma unroll
    for (int i = ty; i < 32; i += 8)
        g_xt[((size_t)b * 32768 + s0 + i) * 256 + c0 + tx] = __float2half(tl[tx][i]);
#pragma unroll
    for (int o = 16; o; o >>= 1) {
        s += __shfl_xor_sync(0xffffffffu, s, o);
        sq += __shfl_xor_sync(0xffffffffu, sq, o);
    }
    if (tx == 0) { red[ty][0] = s; red[ty][1] = sq; }
    __syncthreads();
    if (tx == 0 && ty == 0) {
        float ts = 0.f, tq = 0.f;
#pragma unroll
        for (int i = 0; i < 8; i++) { ts += red[i][0]; tq += red[i][1]; }
        int idx = ((b * 8 + g) * 1024 + blockIdx.x) * 2;
        g_part[idx] = ts; g_part[idx + 1] = tq;
    }
}

__global__ void gn_final_k() {
    __shared__ float red[8][2];
    int gi = blockIdx.x, tid = threadIdx.x;
    float s = 0.f, sq = 0.f;
    for (int i = tid; i < 1024; i += 256) {
        float2 v = *(const float2*)&g_part[(gi * 1024 + i) * 2];
        s += v.x; sq += v.y;
    }
#pragma unroll
    for (int o = 16; o; o >>= 1) {
        s += __shfl_xor_sync(0xffffffffu, s, o);
        sq += __shfl_xor_sync(0xffffffffu, sq, o);
    }
    if ((tid & 31) == 0) { red[tid >> 5][0] = s; red[tid >> 5][1] = sq; }
    __syncthreads();
    if (tid == 0) {
        float ts = 0.f, tq = 0.f;
#pragma unroll
        for (int i = 0; i < 8; i++) { ts += red[i][0]; tq += red[i][1]; }
        const float inv = 1.f / 1048576.f;
        float mean = ts * inv;
        float var = tq * inv - mean * mean;
        g_stat[gi][0] = mean;
        g_stat[gi][1] = rsqrtf(var + EPS);
    }
}

// ---------------- context LayerNorm ----------------
__global__ void ctx_ln_k(const float* __restrict__ ctx, const float* __restrict__ lng,
                         const float* __restrict__ lnb) {
    __shared__ float red[8][2];
    __shared__ float smean, srstd;
    int row = blockIdx.x, tid = threadIdx.x;
    const float* cp = ctx + (size_t)row * 768;
    float v[3]; float s = 0.f, sq = 0.f;
#pragma unroll
    for (int i = 0; i < 3; i++) { v[i] = cp[tid + i * 256]; s += v[i]; sq += v[i] * v[i]; }
#pragma unroll
    for (int o = 16; o; o >>= 1) {
        s += __shfl_xor_sync(0xffffffffu, s, o);
        sq += __shfl_xor_sync(0xffffffffu, sq, o);
    }
    if ((tid & 31) == 0) { red[tid >> 5][0] = s; red[tid >> 5][1] = sq; }
    __syncthreads();
    if (tid == 0) {
        float ts = 0.f, tq = 0.f;
#pragma unroll
        for (int i = 0; i < 8; i++) { ts += red[i][0]; tq += red[i][1]; }
        float mean = ts * (1.f / 768.f);
        float var = tq * (1.f / 768.f) - mean * mean;
        smean = mean; srstd = rsqrtf(var + EPS);
    }
    __syncthreads();
    float mean = smean, rstd = srstd;
#pragma unroll
    for (int i = 0; i < 3; i++) {
        int idx = tid + i * 256;
        g_cn[(size_t)row * 768 + idx] = (v[i] - mean) * rstd * lng[idx] + lnb[idx];
    }
}

// ---------------- K,V projection ----------------
__global__ void kv_proj_k(const float* __restrict__ Wk, const float* __restrict__ Wv) {
    __shared__ float xnt[768 * 8];
    __shared__ float part[3][64][8];
    int tid = threadIdx.x;
    int isV = blockIdx.x >> 2, ct = blockIdx.x & 3;
    int row0 = blockIdx.y * 8;
    const float* W = isV ? Wv : Wk;
#pragma unroll
    for (int r = 0; r < 8; r++) {
        int row = row0 + r;
        for (int i = tid; i < 768; i += 256)
            xnt[i * 8 + r] = (row < 154) ? g_cn[(size_t)row * 768 + i] : 0.f;
    }
    __syncthreads();
    int c = tid & 63, ks = tid >> 6;
    int cg = ct * 64 + c;
    float acc[8];
#pragma unroll
    for (int r = 0; r < 8; r++) acc[r] = 0.f;
    int i0 = ks * 192;
#pragma unroll 8
    for (int i = i0; i < i0 + 192; i++) {
        float w = W[i * 256 + cg];
        float4 a0 = *(const float4*)&xnt[i * 8];
        float4 a1 = *(const float4*)&xnt[i * 8 + 4];
        acc[0] += a0.x * w; acc[1] += a0.y * w; acc[2] += a0.z * w; acc[3] += a0.w * w;
        acc[4] += a1.x * w; acc[5] += a1.y * w; acc[6] += a1.z * w; acc[7] += a1.w * w;
    }
    if (ks > 0) {
#pragma unroll
        for (int r = 0; r < 8; r++) part[ks - 1][c][r] = acc[r];
    }
    __syncthreads();
    if (ks == 0) {
#pragma unroll
        for (int r = 0; r < 8; r++)
            acc[r] += part[0][c][r] + part[1][c][r] + part[2][c][r];
        int h = cg >> 5, d = cg & 31;
#pragma unroll
        for (int r = 0; r < 8; r++) {
            int row = row0 + r;
            if (row < 154) {
                int b = row / 77, j = row % 77;
                if (isV) {
                    g_v[(((size_t)b * HEADS + h) * CTX + j) * 32 + d] = acc[r];
                } else {
                    g_k2[((size_t)b * NP + h * JP + j) * 40 + d] =
                        __float2half(acc[r] * ATT_SCALE);
                }
            }
        }
    }
}

// ---------------- v2t ----------------
__global__ void v2t_k() {
    int n = blockIdx.x, b = blockIdx.y, j = threadIdx.x;
    int h = n >> 5, d = n & 31;
    float v = (j < CTX) ? g_v[(((size_t)b * HEADS + h) * CTX + j) * 32 + d] : 0.f;
    g_v2[((size_t)b * 256 + n) * 88 + j] = __float2half(v);
}

// ---------------- wot ----------------
__global__ void wot_k(const float* __restrict__ Wo) {
    __shared__ float tl[32][33];
    int tx = threadIdx.x, ty = threadIdx.y;
    int u0 = blockIdx.x * 32, c0 = blockIdx.y * 32;
#pragma unroll
    for (int i = ty; i < 32; i += 8)
        tl[i][tx] = Wo[(u0 + i) * 256 + c0 + tx];
    __syncthreads();
#pragma unroll
    for (int i = ty; i < 32; i += 8)
        g_wot[(c0 + i) * 256 + u0 + tx] = __float2half(tl[tx][i]);
}

// ---------------- wqt ----------------
__global__ void wqt_k(const float* __restrict__ Wq, const float* __restrict__ gng,
                      const float* __restrict__ gnb) {
    __shared__ float red[8];
    int n = blockIdx.x, b = blockIdx.y, c = threadIdx.x;
    int g = c >> 5;
    float mean = g_stat[b * 8 + g][0], rstd = g_stat[b * 8 + g][1];
    float ga = gng[c];
    float cA = rstd * ga;
    float cB = gnb[c] - mean * cA;
    float w = Wq[c * 256 + n];
    g_wqt[((size_t)b * 256 + n) * 256 + c] = __float2half(w * cA);
    float bc = cB * w;
#pragma unroll
    for (int o = 16; o; o >>= 1) bc += __shfl_xor_sync(0xffffffffu, bc, o);
    if ((c & 31) == 0) red[c >> 5] = bc;
    __syncthreads();
    if (c == 0) {
        float t = 0.f;
#pragma unroll
        for (int i = 0; i < 8; i++) t += red[i];
        g_qbias[b * 256 + n] = t;
    }
}

// ---------------- gemm1_fused (R11/R13 proven) ----------------
__global__ void __launch_bounds__(512) gemm1_fused() {
    extern __shared__ char smem[];
    uint32_t sb = smem_u32(smem);
    int tid = threadIdx.x, lane = tid & 31, wid = tid >> 5;
    int grp = lane >> 2, lt4 = lane & 3;
    int row0 = blockIdx.x * 128;
    int b = row0 >> 15;

    const __half* Ag = g_xt + (size_t)row0 * 256;
    const __half* Wb = g_wqt + (size_t)b * 65536;
    const __half* Kb = g_k2 + (size_t)b * NP * 40;
    const float* biasb = g_qbias + b * 256;

    for (int id = tid; id < 4096; id += 512) {
        int r = id >> 5, c16 = id & 31;
        cp16(sb + OFF_A + (uint32_t)(r * 264 + c16 * 8) * 2, Ag + r * 256 + c16 * 8);
    }
    for (int id = tid; id < 3200; id += 512) {
        int r = id / 5, c16 = id % 5;
        cp16(sb + OFF_KS + (uint32_t)(r * 40 + c16 * 8) * 2, Kb + r * 40 + c16 * 8);
    }
    cp_commit();

    int smr = tid >> 2, sseg = (tid & 3) * 8;
    uint32_t dstoff = (uint32_t)(smr * 40 + sseg) * 2u;
    auto stageB = [&](int gi) {
        int half = gi >> 3, ki = gi & 7;
        const __half* src = Wb + (size_t)(half * 128 + smr) * 256 + ki * 32 + sseg;
        cp16(sb + ((gi & 1) ? OFF_B1 : OFF_B0) + dstoff, src);
        cp_commit();
    };
    stageB(0);

    int wm0 = (wid & 3) * 32, wn0 = (wid >> 2) * 32;
    uint32_t lrow = (uint32_t)(lane & 15);
    uint32_t lcol = (uint32_t)((lane >> 4) << 3);
    uint32_t aoffb[2], boff1[2];
#pragma unroll
    for (int mf = 0; mf < 2; mf++)
        aoffb[mf] = ((wm0 + mf * 16 + lrow) * 264 + lcol) * 2u;
#pragma unroll
    for (int nfp = 0; nfp < 2; nfp++)
        boff1[nfp] = ((wn0 + nfp * 16 + lrow) * 40 + lcol) * 2u;

    float acc[2][4][4];
#pragma unroll
    for (int a = 0; a < 2; a++)
#pragma unroll
        for (int c = 0; c < 4; c++)
#pragma unroll
            for (int e = 0; e < 4; e++) acc[a][c][e] = 0.f;

    for (int half = 0; half < 2; half++) {
        for (int ki = 0; ki < 8; ki++) {
            int gi = half * 8 + ki;
            if (gi + 1 < 16) { stageB(gi + 1); cp_wait1(); } else cp_wait0();
            __syncthreads();
            uint32_t bB = sb + ((gi & 1) ? OFF_B1 : OFF_B0);
#pragma unroll
            for (int kk = 0; kk < 32; kk += 16) {
                uint32_t af[2][4], bbf[2][4];
#pragma unroll
                for (int mf = 0; mf < 2; mf++)
                    ldsm4(af[mf], sb + OFF_A + aoffb[mf] + (ki * 32 + kk) * 2);
#pragma unroll
                for (int nfp = 0; nfp < 2; nfp++)
                    ldsm4(bbf[nfp], bB + boff1[nfp] + kk * 2);
#pragma unroll
                for (int nf = 0; nf < 4; nf++) {
                    uint32_t b0 = bbf[nf >> 1][nf & 1], b1 = bbf[nf >> 1][2 + (nf & 1)];
#pragma unroll
                    for (int mf = 0; mf < 2; mf++) mma16(acc[mf][nf], af[mf], b0, b1);
                }
            }
            __syncthreads();
        }
        int nh = half * 128;
#pragma unroll
        for (int mf = 0; mf < 2; mf++) {
            int r0 = wm0 + mf * 16 + grp;
#pragma unroll
            for (int nf = 0; nf < 4; nf++) {
                int col = nh + wn0 + nf * 8 + 2 * lt4;
                float2 bv = *(const float2*)(biasb + col);
                __half2 h0 = __floats2half2_rn(acc[mf][nf][0] + bv.x, acc[mf][nf][1] + bv.y);
                __half2 h1 = __floats2half2_rn(acc[mf][nf][2] + bv.x, acc[mf][nf][3] + bv.y);
                *(uint32_t*)(smem + OFF_QT + (uint32_t)(r0 * 264 + col) * 2) = *(uint32_t*)&h0;
                *(uint32_t*)(smem + OFF_QT + (uint32_t)((r0 + 8) * 264 + col) * 2) = *(uint32_t*)&h1;
                acc[mf][nf][0] = acc[mf][nf][1] = acc[mf][nf][2] = acc[mf][nf][3] = 0.f;
            }
        }
    }
    __syncthreads();

    int wm2 = (wid & 3) * 32;
    float acc2[2][10][4];
#pragma unroll 1
    for (int it = 0; it < 2; it++) {
        int h = it * 4 + (wid >> 2);
        uint32_t aoff2[2], boff2[5];
#pragma unroll
        for (int mf = 0; mf < 2; mf++)
            aoff2[mf] = ((wm2 + mf * 16 + lrow) * 264 + h * 32 + lcol) * 2u;
#pragma unroll
        for (int nfp = 0; nfp < 5; nfp++)
            boff2[nfp] = ((h * 80 + nfp * 16 + lrow) * 40 + lcol) * 2u;
#pragma unroll
        for (int a = 0; a < 2; a++)
#pragma unroll
            for (int c = 0; c < 10; c++)
#pragma unroll
                for (int e = 0; e < 4; e++) acc2[a][c][e] = 0.f;
#pragma unroll
        for (int kk = 0; kk < 32; kk += 16) {
            uint32_t af[2][4], bbf[5][4];
#pragma unroll
            for (int mf = 0; mf < 2; mf++)
                ldsm4(af[mf], sb + OFF_QT + aoff2[mf] + kk * 2);
#pragma unroll
            for (int nfp = 0; nfp < 5; nfp++)
                ldsm4(bbf[nfp], sb + OFF_KS + boff2[nfp] + kk * 2);
#pragma unroll
            for (int nf = 0; nf < 10; nf++) {
                uint32_t b0 = bbf[nf >> 1][nf & 1], b1 = bbf[nf >> 1][2 + (nf & 1)];
#pragma unroll
                for (int mf = 0; mf < 2; mf++) mma16(acc2[mf][nf], af[mf], b0, b1);
            }
        }
#pragma unroll
        for (int mf = 0; mf < 2; mf++) {
#pragma unroll
            for (int rh = 0; rh < 2; rh++) {
                int row = wm2 + mf * 16 + grp + rh * 8;
                float m = -1e30f;
#pragma unroll
                for (int nf = 0; nf < 10; nf++) {
#pragma unroll
                    for (int e = 0; e < 2; e++) {
                        int j = nf * 8 + 2 * lt4 + e;
                        float v = (j < CTX) ? acc2[mf][nf][rh * 2 + e] : -1e30f;
                        acc2[mf][nf][rh * 2 + e] = v;
                        m = fmaxf(m, v);
                    }
                }
                m = fmaxf(m, __shfl_xor_sync(0xffffffffu, m, 1));
                m = fmaxf(m, __shfl_xor_sync(0xffffffffu, m, 2));
                float s = 0.f;
#pragma unroll
                for (int nf = 0; nf < 10; nf++) {
#pragma unroll
                    for (int e = 0; e < 2; e++) {
                        int j = nf * 8 + 2 * lt4 + e;
                        float ev = (j < CTX) ? __expf(acc2[mf][nf][rh * 2 + e] - m) : 0.f;
                        acc2[mf][nf][rh * 2 + e] = ev;
                        s += ev;
                    }
                }
                s += __shfl_xor_sync(0xffffffffu, s, 1);
                s += __shfl_xor_sync(0xffffffffu, s, 2);
                float inv = 1.f / s;
                __half* pr = g_p + (size_t)(row0 + row) * NP + h * 80 + 2 * lt4;
#pragma unroll
                for (int nf = 0; nf < 10; nf++) {
                    __half2 hv = __floats2half2_rn(acc2[mf][nf][rh * 2] * inv,
                                                   acc2[mf][nf][rh * 2 + 1] * inv);
                    *(__half2*)(pr + nf * 8) = hv;
                }
            }
        }
    }
}

// ---------------- gemm2_fused: U = P@V (per head), out = U@Wo^T + bo + x ----------------
__global__ void __launch_bounds__(512) gemm2_fused(const float* __restrict__ x,
                                                   const float* __restrict__ bo,
                                                   float* __restrict__ out) {
    extern __shared__ char smem[];
    uint32_t sb = smem_u32(smem);
    int tid = threadIdx.x, lane = tid & 31, wid = tid >> 5;
    int grp = lane >> 2, lt4 = lane & 3;
    int row0 = blockIdx.x * 128;
    int b = row0 >> 15, s0 = row0 & 32767;

    const __half* Ag = g_p + (size_t)row0 * NP;
    const __half* Vb = g_v2 + (size_t)b * 256 * 88;

    uint32_t lrow = (uint32_t)(lane & 15);
    uint32_t lcol = (uint32_t)((lane >> 4) << 3);

    // preload Vt (256x88 -> 2816 chunks)
    for (int id = tid; id < 2816; id += 512) {
        int r = id / 11, c = id % 11;
        cp16(sb + F2_VT + (uint32_t)(r * 88 + c * 8) * 2, Vb + r * 88 + c * 8);
    }
    // stage P head-pair: 128 rows x 2x80 halves = 2560 chunks (5 per thread)
    auto stageP = [&](int pair, int buf) {
#pragma unroll
        for (int i = 0; i < 5; i++) {
            int id = tid + i * 512;
            int r = id / 20, c = id % 20;
            int slot = c / 10, cc = c % 10;
            const __half* src = Ag + (size_t)r * NP + (pair * 2 + slot) * 80 + cc * 8;
            cp16(sb + (buf ? F2_P1 : F2_P0) + (uint32_t)(r * 184 + slot * 96 + cc * 8) * 2, src);
        }
        cp_commit();
    };
    stageP(0, 0);

    // ---- phase 1: warp = 16 rows x 32 d-cols of one head ----
    int slot = wid & 1, mq = wid >> 1;
    uint32_t aoff1 = ((uint32_t)(mq * 16 + lrow) * 184 + slot * 96 + lcol) * 2u;
#pragma unroll 1
    for (int p = 0; p < 4; p++) {
        if (p + 1 < 4) { stageP(p + 1, (p + 1) & 1); cp_wait1(); } else cp_wait0();
        __syncthreads();
        int hd = p * 2 + slot;
        uint32_t pbase = sb + ((p & 1) ? F2_P1 : F2_P0);
        uint32_t boffs[2];
#pragma unroll
        for (int nfp = 0; nfp < 2; nfp++)
            boffs[nfp] = ((uint32_t)(hd * 32 + nfp * 16 + lrow) * 88 + lcol) * 2u;
        float acc[4][4];
#pragma unroll
        for (int c = 0; c < 4; c++)
#pragma unroll
            for (int e = 0; e < 4; e++) acc[c][e] = 0.f;
#pragma unroll
        for (int kk = 0; kk < 80; kk += 16) {
            uint32_t af[4], bbf[2][4];
            ldsm4(af, pbase + aoff1 + kk * 2);
#pragma unroll
            for (int nfp = 0; nfp < 2; nfp++)
                ldsm4(bbf[nfp], sb + F2_VT + boffs[nfp] + kk * 2);
#pragma unroll
            for (int nf = 0; nf < 4; nf++) {
                uint32_t b0 = bbf[nf >> 1][nf & 1], b1 = bbf[nf >> 1][2 + (nf & 1)];
                mma16(acc[nf], af, b0, b1);
            }
        }
        int r0 = mq * 16 + grp;
#pragma unroll
        for (int nf = 0; nf < 4; nf++) {
            int col = hd * 32 + nf * 8 + 2 * lt4;
            __half2 h0 = __floats2half2_rn(acc[nf][0], acc[nf][1]);
            __half2 h1 = __floats2half2_rn(acc[nf][2], acc[nf][3]);
            *(uint32_t*)(smem + F2_U + (uint32_t)(r0 * 264 + col) * 2) = *(uint32_t*)&h0;
            *(uint32_t*)(smem + F2_U + (uint32_t)((r0 + 8) * 264 + col) * 2) = *(uint32_t*)&h1;
        }
        __syncthreads();
    }

    // ---- phase 2: out_tile = U @ Wo^T  (M=128, N=256, K=256) ----
    // FIX (R14 bug): exactly 512 work items — one (row, 16-half segment) per thread.
    auto stageW = [&](int ki, int buf) {
        int r = tid >> 1, c = (tid & 1) * 2;
        const __half* src = g_wot + (size_t)r * 256 + ki * 32 + c * 8;
        uint32_t dst = sb + (buf ? F2_W1 : F2_W0) + (uint32_t)(r * 40 + c * 8) * 2;
        cp16(dst, src);
        cp16(dst + 16, src + 8);
        cp_commit();
    };
    stageW(0, 0);

    int wm = (wid & 1) * 64, wn = (wid >> 1) * 32;
    uint32_t aoff2[4], boff2[2];
#pragma unroll
    for (int mf = 0; mf < 4; mf++)
        aoff2[mf] = ((uint32_t)(wm + mf * 16 + lrow) * 264 + lcol) * 2u;
#pragma unroll
    for (int nfp = 0; nfp < 2; nfp++)
        boff2[nfp] = ((uint32_t)(wn + nfp * 16 + lrow) * 40 + lcol) * 2u;

    float acc[4][4][4];
#pragma unroll
    for (int a = 0; a < 4; a++)
#pragma unroll
        for (int c = 0; c < 4; c++)
#pragma unroll
            for (int e = 0; e < 4; e++) acc[a][c][e] = 0.f;

    for (int ki = 0; ki < 8; ki++) {
        int cur = ki & 1;
        if (ki + 1 < 8) { stageW(ki + 1, cur ^ 1); cp_wait1(); } else cp_wait0();
        __syncthreads();
        uint32_t bB = sb + (cur ? F2_W1 : F2_W0);
#pragma unroll
        for (int kk = 0; kk < 32; kk += 16) {
            uint32_t af[4][4], bbf[2][4];
#pragma unroll
            for (int mf = 0; mf < 4; mf++)
                ldsm4(af[mf], sb + F2_U + aoff2[mf] + (ki * 32 + kk) * 2);
#pragma unroll
            for (int nfp = 0; nfp < 2; nfp++)
                ldsm4(bbf[nfp], bB + boff2[nfp] + kk * 2);
#pragma unroll
            for (int nf = 0; nf < 4; nf++) {
                uint32_t b0 = bbf[nf >> 1][nf & 1], b1 = bbf[nf >> 1][2 + (nf & 1)];
#pragma unroll
                for (int mf = 0; mf < 4; mf++) mma16(acc[mf][nf], af[mf], b0, b1);
            }
        }
        __syncthreads();
    }

    // ---- epilogue: 4-pass transpose bounce + bias + residual ----
    float* bounce = (float*)(smem + F2_P0);
#pragma unroll
    for (int rh = 0; rh < 2; rh++) {
#pragma unroll
        for (int ch = 0; ch < 2; ch++) {
            if ((wid & 1) == rh && (wid >> 1) >= ch * 4 && (wid >> 1) < ch * 4 + 4) {
                int cn0 = wn - ch * 128;
#pragma unroll
                for (int mf = 0; mf < 4; mf++) {
                    int r = mf * 16 + grp;
#pragma unroll
                    for (int nf = 0; nf < 4; nf++) {
                        int c = cn0 + nf * 8 + 2 * lt4;
                        bounce[(c + 0) * 68 + r] = acc[mf][nf][0];
                        bounce[(c + 1) * 68 + r] = acc[mf][nf][1];
                        bounce[(c + 0) * 68 + r + 8] = acc[mf][nf][2];
                        bounce[(c + 1) * 68 + r + 8] = acc[mf][nf][3];
                    }
                }
            }
            __syncthreads();
#pragma unroll
            for (int p = 0; p < 4; p++) {
                int cl = p * 32 + (tid >> 4);
                int sl = (tid & 15) * 4;
                int cg = ch * 128 + cl;
                float4 v = *(const float4*)&bounce[cl * 68 + sl];
                size_t idx = ((size_t)b * 256 + cg) * 32768 + s0 + rh * 64 + sl;
                float4 xv = *(const float4*)(x + idx);
                float bb2 = bo[cg];
                v.x += xv.x + bb2; v.y += xv.y + bb2; v.z += xv.z + bb2; v.w += xv.w + bb2;
                *(float4*)(out + idx) = v;
            }
            __syncthreads();
        }
    }
}

// ---------------- launch ----------------
extern "C" void kernel_launch(void* const* d_in, const int* in_sizes, int n_in,
                              void* d_out, int out_size) {
    const float* x   = (const float*)d_in[0];
    const float* ctx = (const float*)d_in[1];
    const float* gng = (const float*)d_in[2];
    const float* gnb = (const float*)d_in[3];
    const float* lng = (const float*)d_in[4];
    const float* lnb = (const float*)d_in[5];
    const float* Wq  = (const float*)d_in[6];
    const float* Wk  = (const float*)d_in[7];
    const float* Wv  = (const float*)d_in[8];
    const float* Wo  = (const float*)d_in[9];
    const float* bo  = (const float*)d_in[10];
    float* out = (float*)d_out;

    cudaFuncSetAttribute(gemm1_fused, cudaFuncAttributeMaxDynamicSharedMemorySize, SMEM1);
    cudaFuncSetAttribute(gemm2_fused, cudaFuncAttributeMaxDynamicSharedMemorySize, SMEM2F);

    xt_k<<<dim3(1024, 8, 2), dim3(32, 8)>>>(x);
    gn_final_k<<<16, 256>>>();
    ctx_ln_k<<<154, 256>>>(ctx, lng, lnb);
    kv_proj_k<<<dim3(8, 20), 256>>>(Wk, Wv);
    v2t_k<<<dim3(256, NB), 88>>>();
    wot_k<<<dim3(8, 8), dim3(32, 8)>>>(Wo);
    wqt_k<<<dim3(256, 2), 256>>>(Wq, gng, gnb);
    gemm1_fused<<<512, 512, SMEM1>>>();
    gemm2_fused<<<512, 512, SMEM2F>>>(x, bo, out);
}

// round 16
// speedup vs baseline: 1.1690x; 1.1690x over previous
#include <cuda_runtime.h>
#include <cuda_fp16.h>
#include <math.h>
#include <stdint.h>

#define NB 2
#define NC 256
#define NS 32768
#define CTX 77
#define HEADS 8
#define JP 80
#define NP 640
#define M_TOTAL 65536
#define EPS 1e-5f
#define ATT_SCALE 0.17677669529663687f

// ---------------- scratch ----------------
__device__ float g_part[16 * 1024 * 2];
__device__ float g_stat[16][2];
__device__ float g_cn[NB * CTX * 768];
__device__ float g_v[NB * HEADS * CTX * 32];
__device__ __half g_wqt[NB * 256 * 256];
__device__ float g_qbias[NB * 256];
__device__ __half g_k2[NB * NP * 40];             // pads zero from static init
__device__ __half g_v2[NB * 256 * 88];            // V^T per head: [b][h*32+d][j]
__device__ __half g_wot[256 * 256];               // Wo^T fp16: [c][u]
__device__ __half g_xt[(size_t)M_TOTAL * NC];

// ---------------- helpers ----------------
__device__ __forceinline__ uint32_t smem_u32(const void* p) {
    uint32_t a;
    asm("{ .reg .u64 t; cvta.to.shared.u64 t, %1; cvt.u32.u64 %0, t; }" : "=r"(a) : "l"(p));
    return a;
}
__device__ __forceinline__ void cp16(uint32_t dst, const void* src) {
    asm volatile("cp.async.ca.shared.global [%0], [%1], 16;" :: "r"(dst), "l"(src));
}
__device__ __forceinline__ void cp_commit() { asm volatile("cp.async.commit_group;" ::: "memory"); }
__device__ __forceinline__ void cp_wait0() { asm volatile("cp.async.wait_group 0;" ::: "memory"); }
__device__ __forceinline__ void cp_wait1() { asm volatile("cp.async.wait_group 1;" ::: "memory"); }

__device__ __forceinline__ void mma16(float* c, const uint32_t* a, uint32_t b0, uint32_t b1) {
    asm volatile("mma.sync.aligned.m16n8k16.row.col.f32.f16.f16.f32 "
                 "{%0,%1,%2,%3},{%4,%5,%6,%7},{%8,%9},{%0,%1,%2,%3};"
                 : "+f"(c[0]), "+f"(c[1]), "+f"(c[2]), "+f"(c[3])
                 : "r"(a[0]), "r"(a[1]), "r"(a[2]), "r"(a[3]), "r"(b0), "r"(b1));
}
__device__ __forceinline__ void ldsm4(uint32_t* r, uint32_t addr) {
    asm volatile("ldmatrix.sync.aligned.m8n8.x4.shared.b16 {%0,%1,%2,%3}, [%4];"
                 : "=r"(r[0]), "=r"(r[1]), "=r"(r[2]), "=r"(r[3]) : "r"(addr));
}
__device__ __forceinline__ uint32_t h2pack(float a, float b) {
    __half2 h = __floats2half2_rn(a, b);
    return *(uint32_t*)&h;
}

// mega_k smem layout (bytes)
#define M_A0 0u
#define M_A1 10240u
#define M_QT 20480u        // Q then U: 128 x 264 halves = 67584
#define M_KS 88064u        // K: 640 x 40 halves = 51200
#define M_B0 139264u       // Wq stream: 128 x 40 halves
#define M_B1 149504u
#define M_VT 159744u       // Vt: 256 x 88 halves = 45056
#define M_SMEM 204800
#define M_W0 0u            // phase-4 Wo tiles: 256 x 40 halves (A0+A1 area)
#define M_W1 139264u       // (B0+B1 area)
#define M_BOUNCE 88064u    // epilogue bounce (KS area, needs 34816)

// ---------------- xt_k ----------------
__global__ void xt_k(const float* __restrict__ x) {
    __shared__ float tl[32][33];
    __shared__ float red[8][2];
    int tx = threadIdx.x, ty = threadIdx.y;
    int s0 = blockIdx.x * 32, g = blockIdx.y, b = blockIdx.z;
    int c0 = g * 32;
    float s = 0.f, sq = 0.f;
#pragma unroll
    for (int i = ty; i < 32; i += 8) {
        float v = x[((size_t)b * 256 + c0 + i) * 32768 + s0 + tx];
        tl[i][tx] = v;
        s += v; sq += v * v;
    }
    __syncthreads();
#pragma unroll
    for (int i = ty; i < 32; i += 8)
        g_xt[((size_t)b * 32768 + s0 + i) * 256 + c0 + tx] = __float2half(tl[tx][i]);
#pragma unroll
    for (int o = 16; o; o >>= 1) {
        s += __shfl_xor_sync(0xffffffffu, s, o);
        sq += __shfl_xor_sync(0xffffffffu, sq, o);
    }
    if (tx == 0) { red[ty][0] = s; red[ty][1] = sq; }
    __syncthreads();
    if (tx == 0 && ty == 0) {
        float ts = 0.f, tq = 0.f;
#pragma unroll
        for (int i = 0; i < 8; i++) { ts += red[i][0]; tq += red[i][1]; }
        int idx = ((b * 8 + g) * 1024 + blockIdx.x) * 2;
        g_part[idx] = ts; g_part[idx + 1] = tq;
    }
}

__global__ void gn_final_k() {
    __shared__ float red[8][2];
    int gi = blockIdx.x, tid = threadIdx.x;
    float s = 0.f, sq = 0.f;
    for (int i = tid; i < 1024; i += 256) {
        float2 v = *(const float2*)&g_part[(gi * 1024 + i) * 2];
        s += v.x; sq += v.y;
    }
#pragma unroll
    for (int o = 16; o; o >>= 1) {
        s += __shfl_xor_sync(0xffffffffu, s, o);
        sq += __shfl_xor_sync(0xffffffffu, sq, o);
    }
    if ((tid & 31) == 0) { red[tid >> 5][0] = s; red[tid >> 5][1] = sq; }
    __syncthreads();
    if (tid == 0) {
        float ts = 0.f, tq = 0.f;
#pragma unroll
        for (int i = 0; i < 8; i++) { ts += red[i][0]; tq += red[i][1]; }
        const float inv = 1.f / 1048576.f;
        float mean = ts * inv;
        float var = tq * inv - mean * mean;
        g_stat[gi][0] = mean;
        g_stat[gi][1] = rsqrtf(var + EPS);
    }
}

// ---------------- context LayerNorm ----------------
__global__ void ctx_ln_k(const float* __restrict__ ctx, const float* __restrict__ lng,
                         const float* __restrict__ lnb) {
    __shared__ float red[8][2];
    __shared__ float smean, srstd;
    int row = blockIdx.x, tid = threadIdx.x;
    const float* cp = ctx + (size_t)row * 768;
    float v[3]; float s = 0.f, sq = 0.f;
#pragma unroll
    for (int i = 0; i < 3; i++) { v[i] = cp[tid + i * 256]; s += v[i]; sq += v[i] * v[i]; }
#pragma unroll
    for (int o = 16; o; o >>= 1) {
        s += __shfl_xor_sync(0xffffffffu, s, o);
        sq += __shfl_xor_sync(0xffffffffu, sq, o);
    }
    if ((tid & 31) == 0) { red[tid >> 5][0] = s; red[tid >> 5][1] = sq; }
    __syncthreads();
    if (tid == 0) {
        float ts = 0.f, tq = 0.f;
#pragma unroll
        for (int i = 0; i < 8; i++) { ts += red[i][0]; tq += red[i][1]; }
        float mean = ts * (1.f / 768.f);
        float var = tq * (1.f / 768.f) - mean * mean;
        smean = mean; srstd = rsqrtf(var + EPS);
    }
    __syncthreads();
    float mean = smean, rstd = srstd;
#pragma unroll
    for (int i = 0; i < 3; i++) {
        int idx = tid + i * 256;
        g_cn[(size_t)row * 768 + idx] = (v[i] - mean) * rstd * lng[idx] + lnb[idx];
    }
}

// ---------------- K,V projection ----------------
__global__ void kv_proj_k(const float* __restrict__ Wk, const float* __restrict__ Wv) {
    __shared__ float xnt[768 * 8];
    __shared__ float part[3][64][8];
    int tid = threadIdx.x;
    int isV = blockIdx.x >> 2, ct = blockIdx.x & 3;
    int row0 = blockIdx.y * 8;
    const float* W = isV ? Wv : Wk;
#pragma unroll
    for (int r = 0; r < 8; r++) {
        int row = row0 + r;
        for (int i = tid; i < 768; i += 256)
            xnt[i * 8 + r] = (row < 154) ? g_cn[(size_t)row * 768 + i] : 0.f;
    }
    __syncthreads();
    int c = tid & 63, ks = tid >> 6;
    int cg = ct * 64 + c;
    float acc[8];
#pragma unroll
    for (int r = 0; r < 8; r++) acc[r] = 0.f;
    int i0 = ks * 192;
#pragma unroll 8
    for (int i = i0; i < i0 + 192; i++) {
        float w = W[i * 256 + cg];
        float4 a0 = *(const float4*)&xnt[i * 8];
        float4 a1 = *(const float4*)&xnt[i * 8 + 4];
        acc[0] += a0.x * w; acc[1] += a0.y * w; acc[2] += a0.z * w; acc[3] += a0.w * w;
        acc[4] += a1.x * w; acc[5] += a1.y * w; acc[6] += a1.z * w; acc[7] += a1.w * w;
    }
    if (ks > 0) {
#pragma unroll
        for (int r = 0; r < 8; r++) part[ks - 1][c][r] = acc[r];
    }
    __syncthreads();
    if (ks == 0) {
#pragma unroll
        for (int r = 0; r < 8; r++)
            acc[r] += part[0][c][r] + part[1][c][r] + part[2][c][r];
        int h = cg >> 5, d = cg & 31;
#pragma unroll
        for (int r = 0; r < 8; r++) {
            int row = row0 + r;
            if (row < 154) {
                int b = row / 77, j = row % 77;
                if (isV) {
                    g_v[(((size_t)b * HEADS + h) * CTX + j) * 32 + d] = acc[r];
                } else {
                    g_k2[((size_t)b * NP + h * JP + j) * 40 + d] =
                        __float2half(acc[r] * ATT_SCALE);
                }
            }
        }
    }
}

// ---------------- v2t ----------------
__global__ void v2t_k() {
    int n = blockIdx.x, b = blockIdx.y, j = threadIdx.x;
    int h = n >> 5, d = n & 31;
    float v = (j < CTX) ? g_v[(((size_t)b * HEADS + h) * CTX + j) * 32 + d] : 0.f;
    g_v2[((size_t)b * 256 + n) * 88 + j] = __float2half(v);
}

// ---------------- wot ----------------
__global__ void wot_k(const float* __restrict__ Wo) {
    __shared__ float tl[32][33];
    int tx = threadIdx.x, ty = threadIdx.y;
    int u0 = blockIdx.x * 32, c0 = blockIdx.y * 32;
#pragma unroll
    for (int i = ty; i < 32; i += 8)
        tl[i][tx] = Wo[(u0 + i) * 256 + c0 + tx];
    __syncthreads();
#pragma unroll
    for (int i = ty; i < 32; i += 8)
        g_wot[(c0 + i) * 256 + u0 + tx] = __float2half(tl[tx][i]);
}

// ---------------- wqt ----------------
__global__ void wqt_k(const float* __restrict__ Wq, const float* __restrict__ gng,
                      const float* __restrict__ gnb) {
    __shared__ float red[8];
    int n = blockIdx.x, b = blockIdx.y, c = threadIdx.x;
    int g = c >> 5;
    float mean = g_stat[b * 8 + g][0], rstd = g_stat[b * 8 + g][1];
    float ga = gng[c];
    float cA = rstd * ga;
    float cB = gnb[c] - mean * cA;
    float w = Wq[c * 256 + n];
    g_wqt[((size_t)b * 256 + n) * 256 + c] = __float2half(w * cA);
    float bc = cB * w;
#pragma unroll
    for (int o = 16; o; o >>= 1) bc += __shfl_xor_sync(0xffffffffu, bc, o);
    if ((c & 31) == 0) red[c >> 5] = bc;
    __syncthreads();
    if (c == 0) {
        float t = 0.f;
#pragma unroll
        for (int i = 0; i < 8; i++) t += red[i];
        g_qbias[b * 256 + n] = t;
    }
}

// ---------------- mega_k: Q -> S -> softmax -> U=P@V -> out=U@Wo^T + bo + x ----------------
__global__ void __launch_bounds__(512) mega_k(const float* __restrict__ x,
                                              const float* __restrict__ bo,
                                              float* __restrict__ out) {
    extern __shared__ char smem[];
    uint32_t sb = smem_u32(smem);
    int tid = threadIdx.x, lane = tid & 31, wid = tid >> 5;
    int grp = lane >> 2, lt4 = lane & 3;
    int row0 = blockIdx.x * 128;
    int b = row0 >> 15, s0 = row0 & 32767;

    const __half* Ag = g_xt + (size_t)row0 * 256;
    const __half* Wb = g_wqt + (size_t)b * 65536;
    const __half* Kb = g_k2 + (size_t)b * NP * 40;
    const __half* Vb = g_v2 + (size_t)b * 256 * 88;
    const float* biasb = g_qbias + b * 256;

    uint32_t lrow = (uint32_t)(lane & 15);
    uint32_t lcol = (uint32_t)((lane >> 4) << 3);

    // prologue: K + Vt resident loads
    for (int id = tid; id < 3200; id += 512) {
        int r = id / 5, c = id % 5;
        cp16(sb + M_KS + (uint32_t)(r * 40 + c * 8) * 2, Kb + r * 40 + c * 8);
    }
    for (int id = tid; id < 2816; id += 512) {
        int r = id / 11, c = id % 11;
        cp16(sb + M_VT + (uint32_t)(r * 88 + c * 8) * 2, Vb + r * 88 + c * 8);
    }
    cp_commit();

    // ---- phase 1: Q = xt @ Wqt^T (+ bias), A & B both streamed ----
    int smr = tid >> 2, sseg = (tid & 3) * 8;
    uint32_t stoff = (uint32_t)(smr * 40 + sseg) * 2u;
    auto stageAB = [&](int gi) {
        int half = gi >> 3, ki = gi & 7;
        cp16(sb + ((gi & 1) ? M_A1 : M_A0) + stoff, Ag + (size_t)smr * 256 + ki * 32 + sseg);
        cp16(sb + ((gi & 1) ? M_B1 : M_B0) + stoff,
             Wb + (size_t)(half * 128 + smr) * 256 + ki * 32 + sseg);
        cp_commit();
    };
    stageAB(0);

    int wm0 = (wid & 3) * 32, wn0 = (wid >> 2) * 32;
    uint32_t aoffs = ((wm0 + lrow) * 40 + lcol) * 2u;   // per-warp A base (mf adds 16*40*2)
    uint32_t boffs = ((wn0 + lrow) * 40 + lcol) * 2u;

    float acc[2][4][4];
#pragma unroll
    for (int a = 0; a < 2; a++)
#pragma unroll
        for (int c = 0; c < 4; c++)
#pragma unroll
            for (int e = 0; e < 4; e++) acc[a][c][e] = 0.f;

    for (int half = 0; half < 2; half++) {
        for (int ki = 0; ki < 8; ki++) {
            int gi = half * 8 + ki;
            if (gi + 1 < 16) { stageAB(gi + 1); cp_wait1(); } else cp_wait0();
            __syncthreads();
            uint32_t bA = sb + ((gi & 1) ? M_A1 : M_A0);
            uint32_t bB = sb + ((gi & 1) ? M_B1 : M_B0);
#pragma unroll
            for (int kk = 0; kk < 32; kk += 16) {
                uint32_t af[2][4], bbf[2][4];
#pragma unroll
                for (int mf = 0; mf < 2; mf++)
                    ldsm4(af[mf], bA + aoffs + (uint32_t)(mf * 16 * 40 + kk) * 2);
#pragma unroll
                for (int nfp = 0; nfp < 2; nfp++)
                    ldsm4(bbf[nfp], bB + boffs + (uint32_t)(nfp * 16 * 40 + kk) * 2);
#pragma unroll
                for (int nf = 0; nf < 4; nf++) {
                    uint32_t b0 = bbf[nf >> 1][nf & 1], b1 = bbf[nf >> 1][2 + (nf & 1)];
#pragma unroll
                    for (int mf = 0; mf < 2; mf++) mma16(acc[mf][nf], af[mf], b0, b1);
                }
            }
            __syncthreads();
        }
        int nh = half * 128;
#pragma unroll
        for (int mf = 0; mf < 2; mf++) {
            int r0 = wm0 + mf * 16 + grp;
#pragma unroll
            for (int nf = 0; nf < 4; nf++) {
                int col = nh + wn0 + nf * 8 + 2 * lt4;
                float2 bv = *(const float2*)(biasb + col);
                uint32_t h0 = h2pack(acc[mf][nf][0] + bv.x, acc[mf][nf][1] + bv.y);
                uint32_t h1 = h2pack(acc[mf][nf][2] + bv.x, acc[mf][nf][3] + bv.y);
                *(uint32_t*)(smem + M_QT + (uint32_t)(r0 * 264 + col) * 2) = h0;
                *(uint32_t*)(smem + M_QT + (uint32_t)((r0 + 8) * 264 + col) * 2) = h1;
                acc[mf][nf][0] = acc[mf][nf][1] = acc[mf][nf][2] = acc[mf][nf][3] = 0.f;
            }
        }
    }
    __syncthreads();

    // ---- phase 2+3: per head-iteration S, softmax, U = P@V ----
    int wm2 = (wid & 3) * 32;
#pragma unroll 1
    for (int it = 0; it < 2; it++) {
        int h = it * 4 + (wid >> 2);
        uint32_t aoff2[2], boff2[5];
#pragma unroll
        for (int mf = 0; mf < 2; mf++)
            aoff2[mf] = ((wm2 + mf * 16 + lrow) * 264 + h * 32 + lcol) * 2u;
#pragma unroll
        for (int nfp = 0; nfp < 5; nfp++)
            boff2[nfp] = ((h * 80 + nfp * 16 + lrow) * 40 + lcol) * 2u;

        float acc2[2][10][4];
#pragma unroll
        for (int a = 0; a < 2; a++)
#pragma unroll
            for (int c = 0; c < 10; c++)
#pragma unroll
                for (int e = 0; e < 4; e++) acc2[a][c][e] = 0.f;
#pragma unroll
        for (int kk = 0; kk < 32; kk += 16) {
            uint32_t af[2][4], bbf[5][4];
#pragma unroll
            for (int mf = 0; mf < 2; mf++)
                ldsm4(af[mf], sb + M_QT + aoff2[mf] + kk * 2);
#pragma unroll
            for (int nfp = 0; nfp < 5; nfp++)
                ldsm4(bbf[nfp], sb + M_KS + boff2[nfp] + kk * 2);
#pragma unroll
            for (int nf = 0; nf < 10; nf++) {
                uint32_t b0 = bbf[nf >> 1][nf & 1], b1 = bbf[nf >> 1][2 + (nf & 1)];
#pragma unroll
                for (int mf = 0; mf < 2; mf++) mma16(acc2[mf][nf], af[mf], b0, b1);
            }
        }
        __syncthreads();   // all Q reads for this it complete before U overwrites cols

#pragma unroll
        for (int mf = 0; mf < 2; mf++) {
            // softmax per row-half (in place, normalized probs)
#pragma unroll
            for (int rh = 0; rh < 2; rh++) {
                float m = -1e30f;
#pragma unroll
                for (int nf = 0; nf < 10; nf++) {
#pragma unroll
                    for (int e = 0; e < 2; e++) {
                        int j = nf * 8 + 2 * lt4 + e;
                        float v = (j < CTX) ? acc2[mf][nf][rh * 2 + e] : -1e30f;
                        acc2[mf][nf][rh * 2 + e] = v;
                        m = fmaxf(m, v);
                    }
                }
                m = fmaxf(m, __shfl_xor_sync(0xffffffffu, m, 1));
                m = fmaxf(m, __shfl_xor_sync(0xffffffffu, m, 2));
                float s = 0.f;
#pragma unroll
                for (int nf = 0; nf < 10; nf++) {
#pragma unroll
                    for (int e = 0; e < 2; e++) {
                        int j = nf * 8 + 2 * lt4 + e;
                        float ev = (j < CTX) ? __expf(acc2[mf][nf][rh * 2 + e] - m) : 0.f;
                        acc2[mf][nf][rh * 2 + e] = ev;
                        s += ev;
                    }
                }
                s += __shfl_xor_sync(0xffffffffu, s, 1);
                s += __shfl_xor_sync(0xffffffffu, s, 2);
                float inv = 1.f / s;
#pragma unroll
                for (int nf = 0; nf < 10; nf++) {
                    acc2[mf][nf][rh * 2] *= inv;
                    acc2[mf][nf][rh * 2 + 1] *= inv;
                }
            }
            // U = P @ V for this mf: C-frag aliases A-frag (rows grp/grp+8, cols 2*lt4)
            float uacc[4][4];
#pragma unroll
            for (int c = 0; c < 4; c++)
#pragma unroll
                for (int e = 0; e < 4; e++) uacc[c][e] = 0.f;
#pragma unroll
            for (int k5 = 0; k5 < 5; k5++) {
                int k2 = 2 * k5;
                uint32_t af[4];
                af[0] = h2pack(acc2[mf][k2][0], acc2[mf][k2][1]);
                af[1] = h2pack(acc2[mf][k2][2], acc2[mf][k2][3]);
                af[2] = h2pack(acc2[mf][k2 + 1][0], acc2[mf][k2 + 1][1]);
                af[3] = h2pack(acc2[mf][k2 + 1][2], acc2[mf][k2 + 1][3]);
                uint32_t bbf[2][4];
#pragma unroll
                for (int nfp = 0; nfp < 2; nfp++)
                    ldsm4(bbf[nfp],
                          sb + M_VT + ((uint32_t)(h * 32 + nfp * 16 + lrow) * 88 + lcol + k5 * 16) * 2);
#pragma unroll
                for (int nf = 0; nf < 4; nf++) {
                    uint32_t b0 = bbf[nf >> 1][nf & 1], b1 = bbf[nf >> 1][2 + (nf & 1)];
                    mma16(uacc[nf], af, b0, b1);
                }
            }
            // store U fp16 into the dead Q columns (h*32 ..)
            int r0 = wm2 + mf * 16 + grp;
#pragma unroll
            for (int nf = 0; nf < 4; nf++) {
                int col = h * 32 + nf * 8 + 2 * lt4;
                uint32_t h0 = h2pack(uacc[nf][0], uacc[nf][1]);
                uint32_t h1 = h2pack(uacc[nf][2], uacc[nf][3]);
                *(uint32_t*)(smem + M_QT + (uint32_t)(r0 * 264 + col) * 2) = h0;
                *(uint32_t*)(smem + M_QT + (uint32_t)((r0 + 8) * 264 + col) * 2) = h1;
            }
        }
    }
    __syncthreads();

    // ---- phase 4: out_tile = U @ Wo^T (M=128, N=256, K=256) ----
    auto stageW = [&](int ki, int buf) {
        int r = tid >> 1, c = (tid & 1) * 2;
        const __half* src = g_wot + (size_t)r * 256 + ki * 32 + c * 8;
        uint32_t dst = sb + (buf ? M_W1 : M_W0) + (uint32_t)(r * 40 + c * 8) * 2;
        cp16(dst, src);
        cp16(dst + 16, src + 8);
        cp_commit();
    };
    stageW(0, 0);

    int wm = (wid & 1) * 64, wn = (wid >> 1) * 32;
    uint32_t aoff4[4], boff4[2];
#pragma unroll
    for (int mf = 0; mf < 4; mf++)
        aoff4[mf] = ((uint32_t)(wm + mf * 16 + lrow) * 264 + lcol) * 2u;
#pragma unroll
    for (int nfp = 0; nfp < 2; nfp++)
        boff4[nfp] = ((uint32_t)(wn + nfp * 16 + lrow) * 40 + lcol) * 2u;

    float acc4[4][4][4];
#pragma unroll
    for (int a = 0; a < 4; a++)
#pragma unroll
        for (int c = 0; c < 4; c++)
#pragma unroll
            for (int e = 0; e < 4; e++) acc4[a][c][e] = 0.f;

    for (int ki = 0; ki < 8; ki++) {
        int cur = ki & 1;
        if (ki + 1 < 8) { stageW(ki + 1, cur ^ 1); cp_wait1(); } else cp_wait0();
        __syncthreads();
        uint32_t bB = sb + (cur ? M_W1 : M_W0);
#pragma unroll
        for (int kk = 0; kk < 32; kk += 16) {
            uint32_t af[4][4], bbf[2][4];
#pragma unroll
            for (int mf = 0; mf < 4; mf++)
                ldsm4(af[mf], sb + M_QT + aoff4[mf] + (ki * 32 + kk) * 2);
#pragma unroll
            for (int nfp = 0; nfp < 2; nfp++)
                ldsm4(bbf[nfp], bB + boff4[nfp] + kk * 2);
#pragma unroll
            for (int nf = 0; nf < 4; nf++) {
                uint32_t b0 = bbf[nf >> 1][nf & 1], b1 = bbf[nf >> 1][2 + (nf & 1)];
#pragma unroll
                for (int mf = 0; mf < 4; mf++) mma16(acc4[mf][nf], af[mf], b0, b1);
            }
        }
        __syncthreads();
    }

    // ---- epilogue: 4-pass transpose bounce + bias + residual ----
    float* bounce = (float*)(smem + M_BOUNCE);
#pragma unroll
    for (int rh = 0; rh < 2; rh++) {
#pragma unroll
        for (int ch = 0; ch < 2; ch++) {
            if ((wid & 1) == rh && (wid >> 1) >= ch * 4 && (wid >> 1) < ch * 4 + 4) {
                int cn0 = wn - ch * 128;
#pragma unroll
                for (int mf = 0; mf < 4; mf++) {
                    int r = mf * 16 + grp;
#pragma unroll
                    for (int nf = 0; nf < 4; nf++) {
                        int c = cn0 + nf * 8 + 2 * lt4;
                        bounce[(c + 0) * 68 + r] = acc4[mf][nf][0];
                        bounce[(c + 1) * 68 + r] = acc4[mf][nf][1];
                        bounce[(c + 0) * 68 + r + 8] = acc4[mf][nf][2];
                        bounce[(c + 1) * 68 + r + 8] = acc4[mf][nf][3];
                    }
                }
            }
            __syncthreads();
#pragma unroll
            for (int p = 0; p < 4; p++) {
                int cl = p * 32 + (tid >> 4);
                int sl = (tid & 15) * 4;
                int cg = ch * 128 + cl;
                float4 v = *(const float4*)&bounce[cl * 68 + sl];
                size_t idx = ((size_t)b * 256 + cg) * 32768 + s0 + rh * 64 + sl;
                float4 xv = *(const float4*)(x + idx);
                float bb2 = bo[cg];
                v.x += xv.x + bb2; v.y += xv.y + bb2; v.z += xv.z + bb2; v.w += xv.w + bb2;
                *(float4*)(out + idx) = v;
            }
            __syncthreads();
        }
    }
}

// ---------------- launch ----------------
extern "C" void kernel_launch(void* const* d_in, const int* in_sizes, int n_in,
                              void* d_out, int out_size) {
    const float* x   = (const float*)d_in[0];
    const float* ctx = (const float*)d_in[1];
    const float* gng = (const float*)d_in[2];
    const float* gnb = (const float*)d_in[3];
    const float* lng = (const float*)d_in[4];
    const float* lnb = (const float*)d_in[5];
    const float* Wq  = (const float*)d_in[6];
    const float* Wk  = (const float*)d_in[7];
    const float* Wv  = (const float*)d_in[8];
    const float* Wo  = (const float*)d_in[9];
    const float* bo  = (const float*)d_in[10];
    float* out = (float*)d_out;

    cudaFuncSetAttribute(mega_k, cudaFuncAttributeMaxDynamicSharedMemorySize, M_SMEM);

    xt_k<<<dim3(1024, 8, 2), dim3(32, 8)>>>(x);
    gn_final_k<<<16, 256>>>();
    ctx_ln_k<<<154, 256>>>(ctx, lng, lnb);
    kv_proj_k<<<dim3(8, 20), 256>>>(Wk, Wv);
    v2t_k<<<dim3(256, NB), 88>>>();
    wot_k<<<dim3(8, 8), dim3(32, 8)>>>(Wo);
    wqt_k<<<dim3(256, 2), 256>>>(Wq, gng, gnb);
    mega_k<<<512, 512, M_SMEM>>>(x, bo, out);
}